// round 14
// baseline (speedup 1.0000x reference)
#include <cuda_runtime.h>
#include <cuda_fp16.h>
#include <cstdint>
#include <cstddef>

#define BATCH 64
#define T     4096
#define DIN   128
#define DST   256
#define DOUT  128

// ---------------------------------------------------------------------------
// PTX helpers (sm_90+ cluster / mbarrier / st.async)
// ---------------------------------------------------------------------------
__device__ __forceinline__ uint32_t ctarank() {
    uint32_t r; asm("mov.u32 %0, %%cluster_ctarank;" : "=r"(r)); return r;
}
__device__ __forceinline__ uint32_t smem_u32(const void* p) {
    uint32_t a;
    asm("{ .reg .u64 t; cvta.to.shared.u64 t, %1; cvt.u32.u64 %0, t; }"
        : "=r"(a) : "l"(p));
    return a;
}
__device__ __forceinline__ uint32_t mapa_u32(uint32_t l, uint32_t r) {
    uint32_t v; asm("mapa.shared::cluster.u32 %0, %1, %2;" : "=r"(v) : "r"(l), "r"(r));
    return v;
}
__device__ __forceinline__ void mbar_init(uint32_t m, uint32_t cnt) {
    asm volatile("mbarrier.init.shared.b64 [%0], %1;" :: "r"(m), "r"(cnt) : "memory");
}
__device__ __forceinline__ void mbar_expect(uint32_t m, uint32_t tx) {
    asm volatile("mbarrier.arrive.expect_tx.shared.b64 _, [%0], %1;"
                 :: "r"(m), "r"(tx) : "memory");
}
__device__ __forceinline__ void mbar_wait(uint32_t m, uint32_t parity) {
    asm volatile(
        "{\n\t.reg .pred P;\n\t"
        "W_%=:\n\t"
        "mbarrier.try_wait.parity.acquire.cluster.shared::cta.b64 P, [%0], %1, 0x989680;\n\t"
        "@!P bra W_%=;\n\t}"
        :: "r"(m), "r"(parity) : "memory");
}
__device__ __forceinline__ void st_async_b32(uint32_t raddr, uint32_t val, uint32_t rmbar) {
    asm volatile("st.async.shared::cluster.mbarrier::complete_tx::bytes.b32 [%0], %1, [%2];"
                 :: "r"(raddr), "r"(val), "r"(rmbar) : "memory");
}
#define CLUSTER_SYNC() do { \
    asm volatile("barrier.cluster.arrive.aligned;" ::: "memory"); \
    asm volatile("barrier.cluster.wait.aligned;"   ::: "memory"); \
} while (0)

// Exact identity tanh: 1 - 2/(1+e^{2s}).  |err| ~1e-6 (validated R11/R12).
__device__ __forceinline__ float tanh_fast(float s) {
    float e = __expf(2.0f * s);
    return 1.0f - __fdividef(2.0f, e + 1.0f);
}

// 64 HFMA2 over a 128-half (16 uint4) region into 8 chains (8 adds/chain)
#define MAC64(ACC, W, XB) do {                                           \
    const uint4* xp_ = (const uint4*)(XB);                               \
    _Pragma("unroll")                                                    \
    for (int j_ = 0; j_ < 16; j_ += 2) {                                 \
        uint4 v0_ = xp_[j_], v1_ = xp_[j_ + 1];                          \
        (ACC)[0] = __hfma2((W)[4*j_+0], *(__half2*)&v0_.x, (ACC)[0]);    \
        (ACC)[1] = __hfma2((W)[4*j_+1], *(__half2*)&v0_.y, (ACC)[1]);    \
        (ACC)[2] = __hfma2((W)[4*j_+2], *(__half2*)&v0_.z, (ACC)[2]);    \
        (ACC)[3] = __hfma2((W)[4*j_+3], *(__half2*)&v0_.w, (ACC)[3]);    \
        (ACC)[4] = __hfma2((W)[4*j_+4], *(__half2*)&v1_.x, (ACC)[4]);    \
        (ACC)[5] = __hfma2((W)[4*j_+5], *(__half2*)&v1_.y, (ACC)[5]);    \
        (ACC)[6] = __hfma2((W)[4*j_+6], *(__half2*)&v1_.z, (ACC)[6]);    \
        (ACC)[7] = __hfma2((W)[4*j_+7], *(__half2*)&v1_.w, (ACC)[7]);    \
    } } while (0)

#define ZERO8(ACC) do { _Pragma("unroll") \
    for (int k_ = 0; k_ < 8; k_++) (ACC)[k_] = __float2half2_rn(0.f); } while (0)

__device__ __forceinline__ float hsum8a(const __half2* q) {
    float2 a0 = __half22float2(q[0]), a1 = __half22float2(q[1]);
    float2 a2 = __half22float2(q[2]), a3 = __half22float2(q[3]);
    float2 a4 = __half22float2(q[4]), a5 = __half22float2(q[5]);
    float2 a6 = __half22float2(q[6]), a7 = __half22float2(q[7]);
    return (((a0.x+a0.y)+(a1.x+a1.y)) + ((a2.x+a2.y)+(a3.x+a3.y)))
         + (((a4.x+a4.y)+(a5.x+a5.y)) + ((a6.x+a6.y)+(a7.x+a7.y)));
}

// Shared layout (fixed offsets so remote addresses are base + constant)
struct __align__(16) SM {
    __half xo[2][2][128];          // [chain][parity][state]  1024 B
    __half us[2][2][128];          //                         1024 B
    float  pA[2][2][128];          // received A partials     4096 B
    float  pC[2][2][64];           // received C partials     2048 B
    unsigned long long mb[2][2];   // [chain][parity]           32 B
};
#define PA_OFF(c, p) ((uint32_t)(offsetof(SM, pA) + ((c)*2 + (p)) * 512))
#define PC_OFF(c, p) ((uint32_t)(offsetof(SM, pC) + ((c)*2 + (p)) * 256))
#define MB_OFF(c, p) ((uint32_t)(offsetof(SM, mb) + ((c)*2 + (p)) * 8))

// ---------------------------------------------------------------------------
// Dual-chain partial-exchange SSM: 32 clusters x 2 CTAs, 2 batches/cluster.
// Per chain the math is instruction-identical to the passing R12 kernel;
// the second chain's matvecs fill the first chain's wait/tanh bubbles.
// W03 (tid<128, thread i): per chain: B.u_t + A-own full local row; after
//   that chain's wait: tanh(pOwn + recv + bU) -> STS x (CTA-local).
// W47 (thread i): pre-wait: ship lagged C partials + compute/ship A-peer
//   partials (both chains); after each chain's wait: C partial (fills tail),
//   y_{t-2} store for own outputs.
// One __syncthreads per super-step (advances both chains by one t).
// ---------------------------------------------------------------------------
__global__ void __launch_bounds__(256, 1) __cluster_dims__(2, 1, 1)
ssm_fused(const float* __restrict__ u, const float* __restrict__ A,
          const float* __restrict__ B, const float* __restrict__ C,
          float* __restrict__ out)
{
    __shared__ SM sm;
    const int tid = threadIdx.x;
    const bool W47 = tid >= 128;
    const int i = tid & 127;
    const uint32_t rank = ctarank();
    const uint32_t peer = rank ^ 1u;
    const int b0 = (int)((blockIdx.x >> 1) << 1);       // batches b0, b0+1
    const int kcol = (int)rank << 7;
    const bool own_o = W47 && ((i >> 6) == (int)rank);  // warp-uniform
    const int oloc = i & 63;

    const uint32_t lS = smem_u32(&sm);

    if (tid == 0) {
#pragma unroll
        for (int c = 0; c < 2; c++)
#pragma unroll
            for (int p = 0; p < 2; p++) {
                mbar_init(lS + MB_OFF(c, p), 1);
                mbar_expect(lS + MB_OFF(c, p), 768);    // 512 B A + 256 B C
            }
    }
    if (tid < 64) {                                      // x_0 = 0, both chains
        ((uint32_t*)&sm.xo[0][0][0])[tid] = 0u;
        ((uint32_t*)&sm.xo[1][0][0])[tid] = 0u;
    }

    // Register weight tiles (fp32 -> fp16) — SAME slice serves both chains.
    __half2 wX[64], wY[64];
    if (!W47) {
        const int s = ((int)rank << 7) + i;
        const float2* Ar = (const float2*)(A + (size_t)s * DST + kcol);
        const float2* Br = (const float2*)(B + (size_t)s * DIN);
#pragma unroll
        for (int j = 0; j < 64; j++) { float2 v = Ar[j]; wX[j] = __floats2half2_rn(v.x, v.y); }
#pragma unroll
        for (int j = 0; j < 64; j++) { float2 v = Br[j]; wY[j] = __floats2half2_rn(v.x, v.y); }
    } else {
        const int s = ((int)peer << 7) + i;
        const float2* Ar = (const float2*)(A + (size_t)s * DST + kcol);
        const float2* Cr = (const float2*)(C + (size_t)i * DST + kcol);
#pragma unroll
        for (int j = 0; j < 64; j++) { float2 v = Ar[j]; wX[j] = __floats2half2_rn(v.x, v.y); }
#pragma unroll
        for (int j = 0; j < 64; j++) { float2 v = Cr[j]; wY[j] = __floats2half2_rn(v.x, v.y); }
    }

    const float* up0 = u + (size_t)b0 * T * DIN + i;    // chain1 = up0 + T*DIN
    float un0 = 0.f, un1 = 0.f;
    if (!W47) {
        sm.us[0][0][i] = __float2half(up0[0]);
        sm.us[1][0][i] = __float2half(up0[(size_t)T * DIN]);
        un0 = up0[DIN];
        un1 = up0[(size_t)T * DIN + DIN];
    }
    __syncthreads();     // xo[..][0], us[..][0] visible
    CLUSTER_SYNC();      // peer mbarriers armed before any st.async

    const uint32_t rS = mapa_u32(lS, peer);

    __half2 q[8];
    int ph0 = 0, ph1 = 0;
    float sc0 = 0.f, sc1 = 0.f;          // W47: C partial of x_{t-1} (ship/own)
    float* outb0 = out + (size_t)b0 * T * DOUT + i;      // own_o threads only
    float bU0, bU1, pOwn0, pOwn1;

#pragma unroll 1
    for (int t = 0; t < T; ++t) {
        const int cur = t & 1, nxt = cur ^ 1;

        if (W47) {
            // Ship lagged C partial + compute/ship A-peer partial, chain 0
            if (!own_o) st_async_b32(rS + PC_OFF(0, 0) + (uint32_t)(cur*256) + (uint32_t)(oloc<<2),
                                     __float_as_uint(sc0), rS + MB_OFF(0, 0) + (uint32_t)(cur*8));
            ZERO8(q); MAC64(q, wX, sm.xo[0][cur]);
            st_async_b32(rS + PA_OFF(0, 0) + (uint32_t)(cur*512) + (uint32_t)(i<<2),
                         __float_as_uint(hsum8a(q)), rS + MB_OFF(0, 0) + (uint32_t)(cur*8));
            // chain 1
            if (!own_o) st_async_b32(rS + PC_OFF(1, 0) + (uint32_t)(cur*256) + (uint32_t)(oloc<<2),
                                     __float_as_uint(sc1), rS + MB_OFF(1, 0) + (uint32_t)(cur*8));
            ZERO8(q); MAC64(q, wX, sm.xo[1][cur]);
            st_async_b32(rS + PA_OFF(1, 0) + (uint32_t)(cur*512) + (uint32_t)(i<<2),
                         __float_as_uint(hsum8a(q)), rS + MB_OFF(1, 0) + (uint32_t)(cur*8));
        } else {
            ZERO8(q); MAC64(q, wY, sm.us[0][cur]); bU0   = hsum8a(q);
            ZERO8(q); MAC64(q, wX, sm.xo[0][cur]); pOwn0 = hsum8a(q);
            ZERO8(q); MAC64(q, wY, sm.us[1][cur]); bU1   = hsum8a(q);
            ZERO8(q); MAC64(q, wX, sm.xo[1][cur]); pOwn1 = hsum8a(q);
            sm.us[0][nxt][i] = __float2half(un0);        // stage u_{t+1}
            sm.us[1][nxt][i] = __float2half(un1);
            const bool pf = (t + 2 < T);
            un0 = pf ? up0[(size_t)(t + 2) * DIN] : 0.f;
            un1 = pf ? up0[(size_t)(T + t + 2) * DIN] : 0.f;
        }

        // ---- chain 0: wait, finish ----
        if (cur == 0) { mbar_wait(lS + MB_OFF(0,0), ph0); if (tid == 0) mbar_expect(lS + MB_OFF(0,0), 768); }
        else          { mbar_wait(lS + MB_OFF(0,1), ph1); if (tid == 0) mbar_expect(lS + MB_OFF(0,1), 768); }
        if (!W47) {
            const float xv = tanh_fast(pOwn0 + sm.pA[0][cur][i] + bU0);
            const unsigned hv = (unsigned)__half_as_ushort(__float2half_rn(xv));
            const unsigned nb = __shfl_down_sync(0xffffffffu, hv, 1);
            if (!(i & 1)) ((uint32_t*)&sm.xo[0][nxt][0])[i >> 1] = hv | (nb << 16);
        } else {
            ZERO8(q); MAC64(q, wY, sm.xo[0][cur]);       // C partial (fills tail)
            const float fy = hsum8a(q);
            if (own_o && t >= 2) outb0[(size_t)(t - 2) * DOUT] = sc0 + sm.pC[0][cur][oloc];
            sc0 = fy;
        }

        // ---- chain 1: wait, finish ----
        if (cur == 0) { mbar_wait(lS + MB_OFF(1,0), ph0); ph0 ^= 1; if (tid == 0) mbar_expect(lS + MB_OFF(1,0), 768); }
        else          { mbar_wait(lS + MB_OFF(1,1), ph1); ph1 ^= 1; if (tid == 0) mbar_expect(lS + MB_OFF(1,1), 768); }
        if (!W47) {
            const float xv = tanh_fast(pOwn1 + sm.pA[1][cur][i] + bU1);
            const unsigned hv = (unsigned)__half_as_ushort(__float2half_rn(xv));
            const unsigned nb = __shfl_down_sync(0xffffffffu, hv, 1);
            if (!(i & 1)) ((uint32_t*)&sm.xo[1][nxt][0])[i >> 1] = hv | (nb << 16);
        } else {
            ZERO8(q); MAC64(q, wY, sm.xo[1][cur]);
            const float fy = hsum8a(q);
            if (own_o && t >= 2)
                outb0[(size_t)T * DOUT + (size_t)(t - 2) * DOUT] = sc1 + sm.pC[1][cur][oloc];
            sc1 = fy;
        }
        __syncthreads();    // xo[nxt] visible; pA/pC[cur] reads done before reuse
    }

    // ---- Epilogue E0: y[T-2] for both chains (ship pending C + dummy A) ----
    if (W47) {
        if (!own_o) st_async_b32(rS + PC_OFF(0,0) + (uint32_t)(oloc<<2), __float_as_uint(sc0), rS + MB_OFF(0,0));
        st_async_b32(rS + PA_OFF(0,0) + (uint32_t)(i<<2), __float_as_uint(sc0), rS + MB_OFF(0,0));
        if (!own_o) st_async_b32(rS + PC_OFF(1,0) + (uint32_t)(oloc<<2), __float_as_uint(sc1), rS + MB_OFF(1,0));
        st_async_b32(rS + PA_OFF(1,0) + (uint32_t)(i<<2), __float_as_uint(sc1), rS + MB_OFF(1,0));
    }
    mbar_wait(lS + MB_OFF(0,0), ph0);
    if (own_o) outb0[(size_t)(T - 2) * DOUT] = sc0 + sm.pC[0][0][oloc];
    mbar_wait(lS + MB_OFF(1,0), ph0);
    if (own_o) outb0[(size_t)T * DOUT + (size_t)(T - 2) * DOUT] = sc1 + sm.pC[1][0][oloc];
    __syncthreads();

    // ---- Epilogue E1: y[T-1] = C . x_T (x_T lives in xo[c][0]) ----
    float fyT0 = 0.f, fyT1 = 0.f;
    if (W47) {
        ZERO8(q); MAC64(q, wY, sm.xo[0][0]); fyT0 = hsum8a(q);
        if (!own_o) st_async_b32(rS + PC_OFF(0,1) + (uint32_t)(oloc<<2), __float_as_uint(fyT0), rS + MB_OFF(0,1));
        st_async_b32(rS + PA_OFF(0,1) + (uint32_t)(i<<2), __float_as_uint(fyT0), rS + MB_OFF(0,1));
        ZERO8(q); MAC64(q, wY, sm.xo[1][0]); fyT1 = hsum8a(q);
        if (!own_o) st_async_b32(rS + PC_OFF(1,1) + (uint32_t)(oloc<<2), __float_as_uint(fyT1), rS + MB_OFF(1,1));
        st_async_b32(rS + PA_OFF(1,1) + (uint32_t)(i<<2), __float_as_uint(fyT1), rS + MB_OFF(1,1));
    }
    mbar_wait(lS + MB_OFF(0,1), ph1);
    if (own_o) outb0[(size_t)(T - 1) * DOUT] = fyT0 + sm.pC[0][1][oloc];
    mbar_wait(lS + MB_OFF(1,1), ph1);
    if (own_o) outb0[(size_t)T * DOUT + (size_t)(T - 1) * DOUT] = fyT1 + sm.pC[1][1][oloc];
    CLUSTER_SYNC();                                // no early exit under peer traffic
}

// ---------------------------------------------------------------------------
// Single launch: 64 CTAs = 32 two-CTA clusters, 2 batches per cluster.
// ---------------------------------------------------------------------------
extern "C" void kernel_launch(void* const* d_in, const int* in_sizes, int n_in,
                              void* d_out, int out_size) {
    const float* u = (const float*)d_in[0];   // [64,4096,128]
    const float* A = (const float*)d_in[1];   // [256,256]
    const float* B = (const float*)d_in[2];   // [256,128]
    const float* C = (const float*)d_in[3];   // [128,256]
    float* out = (float*)d_out;               // [64,4096,128]

    ssm_fused<<<BATCH, 256>>>(u, A, B, C, out);
}

// round 15
// speedup vs baseline: 2.4558x; 2.4558x over previous
#include <cuda_runtime.h>
#include <cuda_fp16.h>
#include <cstdint>
#include <cstddef>

#define BATCH 64
#define T     4096
#define DIN   128
#define DST   256
#define DOUT  128

// ---------------------------------------------------------------------------
// PTX helpers
// ---------------------------------------------------------------------------
__device__ __forceinline__ uint32_t ctarank() {
    uint32_t r; asm("mov.u32 %0, %%cluster_ctarank;" : "=r"(r)); return r;
}
__device__ __forceinline__ uint32_t smem_u32(const void* p) {
    uint32_t a;
    asm("{ .reg .u64 t; cvta.to.shared.u64 t, %1; cvt.u32.u64 %0, t; }"
        : "=r"(a) : "l"(p));
    return a;
}
__device__ __forceinline__ uint32_t mapa_u32(uint32_t l, uint32_t r) {
    uint32_t v; asm("mapa.shared::cluster.u32 %0, %1, %2;" : "=r"(v) : "r"(l), "r"(r));
    return v;
}
__device__ __forceinline__ void mbar_init(uint32_t m, uint32_t cnt) {
    asm volatile("mbarrier.init.shared.b64 [%0], %1;" :: "r"(m), "r"(cnt) : "memory");
}
__device__ __forceinline__ void mbar_expect(uint32_t m, uint32_t tx) {
    asm volatile("mbarrier.arrive.expect_tx.shared.b64 _, [%0], %1;"
                 :: "r"(m), "r"(tx) : "memory");
}
__device__ __forceinline__ void mbar_wait(uint32_t m, uint32_t parity) {
    asm volatile(
        "{\n\t.reg .pred P;\n\t"
        "W_%=:\n\t"
        "mbarrier.try_wait.parity.acquire.cluster.shared::cta.b64 P, [%0], %1, 0x989680;\n\t"
        "@!P bra W_%=;\n\t}"
        :: "r"(m), "r"(parity) : "memory");
}
__device__ __forceinline__ void st_async_b32(uint32_t raddr, uint32_t val, uint32_t rmbar) {
    asm volatile("st.async.shared::cluster.mbarrier::complete_tx::bytes.b32 [%0], %1, [%2];"
                 :: "r"(raddr), "r"(val), "r"(rmbar) : "memory");
}
#define CLUSTER_SYNC() do { \
    asm volatile("barrier.cluster.arrive.aligned;" ::: "memory"); \
    asm volatile("barrier.cluster.wait.aligned;"   ::: "memory"); \
} while (0)

// Exact identity tanh: 1 - 2/(1+e^{2s}).  |err| ~1e-6 (validated R11-R13).
__device__ __forceinline__ float tanh_fast(float s) {
    float e = __expf(2.0f * s);
    return 1.0f - __fdividef(2.0f, e + 1.0f);
}

// 64 HFMA2 over 128 halfs (16 uint4) into 8 half2 chains (8 adds each)
#define MAC64(ACC, W, XB) do {                                           \
    const uint4* xp_ = (const uint4*)(XB);                               \
    _Pragma("unroll")                                                    \
    for (int j_ = 0; j_ < 16; j_ += 2) {                                 \
        uint4 v0_ = xp_[j_], v1_ = xp_[j_ + 1];                          \
        (ACC)[0] = __hfma2((W)[4*j_+0], *(__half2*)&v0_.x, (ACC)[0]);    \
        (ACC)[1] = __hfma2((W)[4*j_+1], *(__half2*)&v0_.y, (ACC)[1]);    \
        (ACC)[2] = __hfma2((W)[4*j_+2], *(__half2*)&v0_.z, (ACC)[2]);    \
        (ACC)[3] = __hfma2((W)[4*j_+3], *(__half2*)&v0_.w, (ACC)[3]);    \
        (ACC)[4] = __hfma2((W)[4*j_+4], *(__half2*)&v1_.x, (ACC)[4]);    \
        (ACC)[5] = __hfma2((W)[4*j_+5], *(__half2*)&v1_.y, (ACC)[5]);    \
        (ACC)[6] = __hfma2((W)[4*j_+6], *(__half2*)&v1_.z, (ACC)[6]);    \
        (ACC)[7] = __hfma2((W)[4*j_+7], *(__half2*)&v1_.w, (ACC)[7]);    \
    } } while (0)

// 32 HFMA2 over 64 halfs (8 uint4) into 8 half2 chains (4 adds each)
#define MAC32(ACC, W, XB) do {                                           \
    const uint4* xp_ = (const uint4*)(XB);                               \
    _Pragma("unroll")                                                    \
    for (int j_ = 0; j_ < 8; j_ += 2) {                                  \
        uint4 v0_ = xp_[j_], v1_ = xp_[j_ + 1];                          \
        (ACC)[0] = __hfma2((W)[4*j_+0], *(__half2*)&v0_.x, (ACC)[0]);    \
        (ACC)[1] = __hfma2((W)[4*j_+1], *(__half2*)&v0_.y, (ACC)[1]);    \
        (ACC)[2] = __hfma2((W)[4*j_+2], *(__half2*)&v0_.z, (ACC)[2]);    \
        (ACC)[3] = __hfma2((W)[4*j_+3], *(__half2*)&v0_.w, (ACC)[3]);    \
        (ACC)[4] = __hfma2((W)[4*j_+4], *(__half2*)&v1_.x, (ACC)[4]);    \
        (ACC)[5] = __hfma2((W)[4*j_+5], *(__half2*)&v1_.y, (ACC)[5]);    \
        (ACC)[6] = __hfma2((W)[4*j_+6], *(__half2*)&v1_.z, (ACC)[6]);    \
        (ACC)[7] = __hfma2((W)[4*j_+7], *(__half2*)&v1_.w, (ACC)[7]);    \
    } } while (0)

#define ZERO8(ACC) do { _Pragma("unroll") \
    for (int k_ = 0; k_ < 8; k_++) (ACC)[k_] = __float2half2_rn(0.f); } while (0)

__device__ __forceinline__ float hsum8a(const __half2* q) {
    float2 a0 = __half22float2(q[0]), a1 = __half22float2(q[1]);
    float2 a2 = __half22float2(q[2]), a3 = __half22float2(q[3]);
    float2 a4 = __half22float2(q[4]), a5 = __half22float2(q[5]);
    float2 a6 = __half22float2(q[6]), a7 = __half22float2(q[7]);
    return (((a0.x+a0.y)+(a1.x+a1.y)) + ((a2.x+a2.y)+(a3.x+a3.y)))
         + (((a4.x+a4.y)+(a5.x+a5.y)) + ((a6.x+a6.y)+(a7.x+a7.y)));
}

// Shared layout (identical on both CTAs; fixed offsets for remote addressing)
struct __align__(16) SM {
    __half xs[2][256];             // CTA0: local x ring            1024 B
    __half xb[2][256];             // CTA1: received x ring         1024 B
    __half us[2][128];             // CTA1: u staging                512 B
    float  pBu[2][256];            // CTA0: received B.u ring       2048 B
    float  psC[128];               // CTA1: y half-combine           512 B
    unsigned long long mbA[2];     // CTA0: pBu arrival
    unsigned long long mbB[2];     // CTA1: x arrival
};
#define XS_OFF   ((uint32_t)offsetof(SM, xs))
#define XB_OFF   ((uint32_t)offsetof(SM, xb))
#define PBU_OFF  ((uint32_t)offsetof(SM, pBu))
#define MBA_OFF  ((uint32_t)offsetof(SM, mbA))
#define MBB_OFF  ((uint32_t)offsetof(SM, mbB))

// ---------------------------------------------------------------------------
// Pipelined-role SSM: 64 clusters x 2 CTAs, one batch per cluster.
// CTA0 (recurrence engine): thread s holds the FULL A row in 128 half2 regs.
//   step t: A.x_t (128 HFMA2, CTA-local x) -> wait pBu(t) (pre-delivered,
//   fast-path) -> tanh -> STS x_{t+1} + st.async x_{t+1} to CTA1 -> bar.
//   Nothing inter-CTA is on the dependent chain except the (early) pBu wait.
// CTA1 (co-processor): iter k: B.u_{k+2} matvec; wait x_{k+1}; y_k = C.x_{k+1}
//   (two 64-chunks, fp32 combine); ship pBu(k+2) AFTER the x reads (this is
//   CTA0's buffer-release token); y store. x receipt is CTA1's release token
//   for the pBu slot. Credit-free, deadlock-free by construction.
// ---------------------------------------------------------------------------
__global__ void __launch_bounds__(256, 1) __cluster_dims__(2, 1, 1)
ssm_fused(const float* __restrict__ u, const float* __restrict__ A,
          const float* __restrict__ B, const float* __restrict__ C,
          float* __restrict__ out)
{
    __shared__ SM sm;
    const int tid = threadIdx.x;
    const int i = tid;
    const uint32_t rank = ctarank();
    const uint32_t peer = rank ^ 1u;
    const int b = blockIdx.x >> 1;
    const uint32_t lS = smem_u32(&sm);

    if (tid == 0) {
        mbar_init(lS + MBA_OFF, 1);     mbar_init(lS + MBA_OFF + 8, 1);
        mbar_init(lS + MBB_OFF, 1);     mbar_init(lS + MBB_OFF + 8, 1);
        mbar_expect(lS + MBA_OFF, 1024); mbar_expect(lS + MBA_OFF + 8, 1024);
        mbar_expect(lS + MBB_OFF, 512);  mbar_expect(lS + MBB_OFF + 8, 512);
    }
    if (rank == 0 && tid < 128)
        ((uint32_t*)&sm.xs[0][0])[tid] = 0u;          // x_0 = 0

    // Weight registers: 128 half2 on both roles.
    //  CTA0: w0 = A[i][0:128), w1 = A[i][128:256)
    //  CTA1: w0 = B[i][0:128);  w1 = C[o][h*128 .. +128)  (o=i&127, h=i>>7)
    __half2 w0[64], w1[64];
    const int o = i & 127, h = i >> 7;
    if (rank == 0) {
        const float2* Ar = (const float2*)(A + (size_t)i * DST);
#pragma unroll
        for (int j = 0; j < 64; j++) { float2 v = Ar[j];      w0[j] = __floats2half2_rn(v.x, v.y); }
#pragma unroll
        for (int j = 0; j < 64; j++) { float2 v = Ar[64 + j]; w1[j] = __floats2half2_rn(v.x, v.y); }
    } else {
        const float2* Br = (const float2*)(B + (size_t)i * DIN);
#pragma unroll
        for (int j = 0; j < 64; j++) { float2 v = Br[j]; w0[j] = __floats2half2_rn(v.x, v.y); }
        const float2* Cr = (const float2*)(C + (size_t)o * DST + (h << 7));
#pragma unroll
        for (int j = 0; j < 64; j++) { float2 v = Cr[j]; w1[j] = __floats2half2_rn(v.x, v.y); }
    }

    __syncthreads();
    CLUSTER_SYNC();      // mbarriers armed on both CTAs before any st.async
    const uint32_t rS = mapa_u32(lS, peer);

    __half2 q[8];
    int ph[2] = {0, 0};

    if (rank == 0) {
        // ================= CTA0: recurrence engine =================
#pragma unroll 1
        for (int t = 0; t < T; ++t) {
            const int cur = t & 1, nxt = cur ^ 1;
            const __half* xc = sm.xs[cur];

            ZERO8(q);
            MAC64(q, w0, xc);            // A[i][0:128) . x[0:128)
            MAC64(q, w1, xc + 128);      // A[i][128:256) . x[128:256)
            const float fA = hsum8a(q);

            const uint32_t mb = lS + MBA_OFF + (uint32_t)(cur * 8);
            mbar_wait(mb, ph[cur]); ph[cur] ^= 1;        // pBu(t) — pre-delivered
            if (tid == 0) mbar_expect(mb, 1024);

            const float xv = tanh_fast(fA + sm.pBu[cur][i]);
            const unsigned hv = (unsigned)__half_as_ushort(__float2half_rn(xv));
            const unsigned nb = __shfl_down_sync(0xffffffffu, hv, 1);
            if (!(i & 1)) {
                const unsigned pk = hv | (nb << 16);
                ((uint32_t*)&sm.xs[nxt][0])[i >> 1] = pk;              // local
                st_async_b32(rS + XB_OFF + (uint32_t)(nxt * 512) + (uint32_t)(i << 1),
                             pk, rS + MBB_OFF + (uint32_t)(nxt * 8));  // to CTA1
            }
            __syncthreads();
        }
    } else {
        // ================= CTA1: B.u producer + y consumer =================
        const float* ub = u + (size_t)b * T * DIN + o;   // threads i<128 load

        // Pre-loop: stage u_0, u_1; ship pBu(0), pBu(1)
        if (i < 128) {
            sm.us[0][i] = __float2half(ub[0]);
            sm.us[1][i] = __float2half(ub[DIN]);
        }
        __syncthreads();
        ZERO8(q); MAC64(q, w0, sm.us[0]);
        st_async_b32(rS + PBU_OFF + (uint32_t)(i << 2),
                     __float_as_uint(hsum8a(q)), rS + MBA_OFF);
        ZERO8(q); MAC64(q, w0, sm.us[1]);
        st_async_b32(rS + PBU_OFF + 1024u + (uint32_t)(i << 2),
                     __float_as_uint(hsum8a(q)), rS + MBA_OFF + 8u);
        __syncthreads();                                  // us reads done
        float un = (i < 128) ? ub[(size_t)2 * DIN] : 0.f; // u_2

#pragma unroll 1
        for (int k = 0; k < T; ++k) {
            const int cur = k & 1;
            if (i < 128) sm.us[cur][i] = __float2half(un);   // u_{k+2}
            __syncthreads();                                  // bar0

            ZERO8(q); MAC64(q, w0, sm.us[cur]);               // B . u_{k+2}
            const float pship = hsum8a(q);
            un = (i < 128 && k + 3 < T) ? ub[(size_t)(k + 3) * DIN] : 0.f;

            const int xsl = (k + 1) & 1;                      // wait x_{k+1}
            const uint32_t mb = lS + MBB_OFF + (uint32_t)(xsl * 8);
            mbar_wait(mb, ph[xsl]); ph[xsl] ^= 1;
            if (tid == 0) mbar_expect(mb, 512);

            const __half* xk = sm.xb[xsl] + (h << 7);
            ZERO8(q); MAC32(q, w1, xk);                       // C chunk 1 (64)
            float fy = hsum8a(q);
            ZERO8(q); MAC32(q, w1 + 32, xk + 64);             // C chunk 2 (64)
            fy += hsum8a(q);

            // Release token: pBu(k+2) ships only after our x_{k+1} reads
            if (k + 2 < T)
                st_async_b32(rS + PBU_OFF + (uint32_t)(cur * 1024) + (uint32_t)(i << 2),
                             __float_as_uint(pship), rS + MBA_OFF + (uint32_t)(cur * 8));

            if (h) sm.psC[o] = fy;
            __syncthreads();                                  // bar1
            if (!h) out[((size_t)b * T + k) * DOUT + o] = fy + sm.psC[o];
        }
    }
    CLUSTER_SYNC();      // no early exit while peer traffic may be in flight
}

// ---------------------------------------------------------------------------
// Single launch: 128 CTAs = 64 two-CTA clusters, one wave.
// ---------------------------------------------------------------------------
extern "C" void kernel_launch(void* const* d_in, const int* in_sizes, int n_in,
                              void* d_out, int out_size) {
    const float* u = (const float*)d_in[0];   // [64,4096,128]
    const float* A = (const float*)d_in[1];   // [256,256]
    const float* B = (const float*)d_in[2];   // [256,128]
    const float* C = (const float*)d_in[3];   // [128,256]
    float* out = (float*)d_out;               // [64,4096,128]

    ssm_fused<<<BATCH * 2, 256>>>(u, A, B, C, out);
}